// round 12
// baseline (speedup 1.0000x reference)
#include <cuda_runtime.h>
#include <cuda_fp16.h>
#include <mma.h>
#include <math_constants.h>
#include <cstdint>
#include <cstddef>

using namespace nvcuda;

// Problem constants
#define KB 8
#define KS 4096
#define KH 16
#define KD 1024
#define KM 32768      // B*S
#define KW 16

// Device scratch (allocation-free rules)
__device__ __align__(256) __half g_qkvh [(size_t)KM * 3072];  // fp16 QKV (+bias)
__device__ __align__(256) __half g_xh   [(size_t)KM * KD];    // x in fp16
__device__ __align__(256) __half g_attnh[(size_t)KM * KD];    // attention out fp16
__device__ __align__(256) __half g_wqkvh[1024 * 3072];        // Wqkv fp16 [K][N]
__device__ __align__(256) __half g_woh  [1024 * 1024];        // Wo   fp16 [K][N]

// ---------------------------------------------------------------------------
// PTX helpers
// ---------------------------------------------------------------------------
__device__ __forceinline__ uint32_t smem_u32(const void* p) {
    return (uint32_t)__cvta_generic_to_shared((void*)p);
}
__device__ __forceinline__ void cp_async16(uint32_t dst, const void* src) {
    asm volatile("cp.async.cg.shared.global [%0], [%1], 16;\n" :: "r"(dst), "l"(src) : "memory");
}
__device__ __forceinline__ void cp_commit() { asm volatile("cp.async.commit_group;\n" ::: "memory"); }
__device__ __forceinline__ void cp_wait0()  { asm volatile("cp.async.wait_group 0;\n" ::: "memory"); }
__device__ __forceinline__ void cp_wait1()  { asm volatile("cp.async.wait_group 1;\n" ::: "memory"); }

__device__ __forceinline__ void ldsm_x4(uint32_t& r0, uint32_t& r1, uint32_t& r2, uint32_t& r3,
                                        uint32_t addr) {
    asm volatile("ldmatrix.sync.aligned.m8n8.x4.shared.b16 {%0,%1,%2,%3}, [%4];"
                 : "=r"(r0), "=r"(r1), "=r"(r2), "=r"(r3) : "r"(addr));
}
__device__ __forceinline__ void ldsm_x4_t(uint32_t& r0, uint32_t& r1, uint32_t& r2, uint32_t& r3,
                                          uint32_t addr) {
    asm volatile("ldmatrix.sync.aligned.m8n8.x4.trans.shared.b16 {%0,%1,%2,%3}, [%4];"
                 : "=r"(r0), "=r"(r1), "=r"(r2), "=r"(r3) : "r"(addr));
}
__device__ __forceinline__ void mma16816(float* d, const uint32_t* a, uint32_t b0, uint32_t b1) {
    asm volatile("mma.sync.aligned.m16n8k16.row.col.f32.f16.f16.f32 "
                 "{%0,%1,%2,%3}, {%4,%5,%6,%7}, {%8,%9}, {%0,%1,%2,%3};"
                 : "+f"(d[0]), "+f"(d[1]), "+f"(d[2]), "+f"(d[3])
                 : "r"(a[0]), "r"(a[1]), "r"(a[2]), "r"(a[3]), "r"(b0), "r"(b1));
}

// ---------------------------------------------------------------------------
// fp32 -> fp16 convert
// ---------------------------------------------------------------------------
__global__ void f2h(const float* __restrict__ in, __half* __restrict__ out, int n)
{
    int i = (blockIdx.x * blockDim.x + threadIdx.x) * 4;
    const int stride = gridDim.x * blockDim.x * 4;
    for (; i < n; i += stride) {
        float4 v = *(const float4*)(in + i);
        __half2 h0 = __floats2half2_rn(v.x, v.y);
        __half2 h1 = __floats2half2_rn(v.z, v.w);
        uint2 u;
        u.x = *reinterpret_cast<uint32_t*>(&h0);
        u.y = *reinterpret_cast<uint32_t*>(&h1);
        *(uint2*)(out + i) = u;
    }
}

// ---------------------------------------------------------------------------
// Raw mma.sync fp16 GEMM: C[M,N] = A[M,K]h @ B[K,N]h + bias[N]
// CTA 128x128, BK=64 (16 iters), 8 warps (2x4), warp tile 64x32.
// 3-stage cp.async ring, 1 sync/iter. Register-pipelined fragments:
// ldmatrix for k-step kk+1 issued BEFORE the 16 MMAs of step kk.
// Direct gmem epilogue (no smem staging). 2 CTAs/SM.
// ---------------------------------------------------------------------------
#define G_LDA 72                     // A row stride (halves)
#define G_LDB 136                    // B row stride (halves)
#define G_ASZ (128 * G_LDA * 2)      // 18432
#define G_STG (G_ASZ + 64 * G_LDB * 2)   // 35840
#define G_SMEM (3 * G_STG)           // 107520

template<bool HALF_OUT>
__global__ __launch_bounds__(256, 2)
void gemm_mma(const __half* __restrict__ A, const __half* __restrict__ Bw,
              const float* __restrict__ bias, void* __restrict__ Cv,
              int N, int K)
{
    extern __shared__ __align__(16) char sm[];
    const uint32_t sbase = smem_u32(sm);
    const int tid    = threadIdx.x;
    const int warpId = tid >> 5;
    const int lane   = tid & 31;
    const int wm = warpId & 1;        // 64-row half
    const int wn = warpId >> 1;       // 32-col quarter
    const int m0 = blockIdx.y * 128;
    const int n0 = blockIdx.x * 128;
    const int nT = K >> 6;            // 16

    // Per-lane ldmatrix byte offsets within a stage slot.
    // A (x4, no trans): rows (wm*64 + i*16 + (lane&15)), col kk*16 + ((lane>>4)&1)*8
    const uint32_t offA = (uint32_t)(((wm * 64 + (lane & 15)) * G_LDA
                                      + ((lane >> 4) & 1) * 8) * 2);
    // B (x4, trans): row kk*16 + (lane&7) + ((lane>>4)&1)*8, col wn*32 + w16*16 + ((lane>>3)&1)*8
    const uint32_t offB = (uint32_t)(G_ASZ
                          + (((lane & 7) + ((lane >> 4) & 1) * 8) * G_LDB
                             + wn * 32 + ((lane >> 3) & 1) * 8) * 2);

    auto fill = [&](int t, int slot) {
        const int k0 = t << 6;
        const uint32_t sb = sbase + (uint32_t)slot * G_STG;
#pragma unroll
        for (int u = 0; u < 4; u++) {
            int i = tid + u * 256;
            int r = i >> 3, c = (i & 7) * 8;
            cp_async16(sb + r * (G_LDA * 2) + c * 2, A + (size_t)(m0 + r) * K + k0 + c);
        }
#pragma unroll
        for (int u = 0; u < 4; u++) {
            int i = tid + u * 256;
            int r = i >> 4, c = (i & 15) * 8;
            cp_async16(sb + G_ASZ + r * (G_LDB * 2) + c * 2,
                       Bw + (size_t)(k0 + r) * N + n0 + c);
        }
    };

    fill(0, 0); cp_commit();
    fill(1, 1); cp_commit();

    // Accumulators: 4 m-tiles x 4 n-atoms x 4 regs = 64
    float acc[16][4];
#pragma unroll
    for (int i = 0; i < 16; i++)
#pragma unroll
        for (int e = 0; e < 4; e++) acc[i][e] = 0.0f;

    // Fragment double buffers: A[buf][mtile][4], B[buf][w16][4]
    uint32_t aF[2][4][4];
    uint32_t bF[2][2][4];

    for (int t = 0; t < nT; t++) {
        const int slot = t % 3;
        if (t + 1 < nT) cp_wait1(); else cp_wait0();
        __syncthreads();
        if (t + 2 < nT) { fill(t + 2, (t + 2) % 3); cp_commit(); }

        const uint32_t sb = sbase + (uint32_t)slot * G_STG;
        const uint32_t aAddr = sb + offA;
        const uint32_t bAddr = sb + offB;

        // load k-step 0 fragments
#pragma unroll
        for (int i = 0; i < 4; i++)
            ldsm_x4(aF[0][i][0], aF[0][i][1], aF[0][i][2], aF[0][i][3],
                    aAddr + (uint32_t)(i * 16 * G_LDA * 2));
#pragma unroll
        for (int w16 = 0; w16 < 2; w16++)
            ldsm_x4_t(bF[0][w16][0], bF[0][w16][1], bF[0][w16][2], bF[0][w16][3],
                      bAddr + (uint32_t)(w16 * 32));

#pragma unroll
        for (int kk = 0; kk < 4; kk++) {
            const int cur = kk & 1;
            if (kk < 3) {
                const int nxt = cur ^ 1;
                const uint32_t ka = aAddr + (uint32_t)((kk + 1) * 32);
                const uint32_t kb = bAddr + (uint32_t)((kk + 1) * 16 * G_LDB * 2);
#pragma unroll
                for (int i = 0; i < 4; i++)
                    ldsm_x4(aF[nxt][i][0], aF[nxt][i][1], aF[nxt][i][2], aF[nxt][i][3],
                            ka + (uint32_t)(i * 16 * G_LDA * 2));
#pragma unroll
                for (int w16 = 0; w16 < 2; w16++)
                    ldsm_x4_t(bF[nxt][w16][0], bF[nxt][w16][1], bF[nxt][w16][2], bF[nxt][w16][3],
                              kb + (uint32_t)(w16 * 32));
            }
#pragma unroll
            for (int i = 0; i < 4; i++) {
#pragma unroll
                for (int n = 0; n < 4; n++) {
                    // n-atom n: ldsm group n>>1, regs {n&1, 2+(n&1)}
                    mma16816(acc[i * 4 + n], aF[cur][i],
                             bF[cur][n >> 1][n & 1], bF[cur][n >> 1][2 + (n & 1)]);
                }
            }
        }
    }

    // ---- direct epilogue: bias + stores (no smem) ----
    const int rB = lane >> 2;          // row within 16-tile
    const int cB = (lane & 3) * 2;     // col pair within 8-atom
#pragma unroll
    for (int n = 0; n < 4; n++) {
        const int col = n0 + wn * 32 + n * 8 + cB;
        const float2 bb = *(const float2*)(bias + col);
#pragma unroll
        for (int i = 0; i < 4; i++) {
            const size_t r0 = (size_t)(m0 + wm * 64 + i * 16 + rB);
            const float v0 = acc[i * 4 + n][0] + bb.x;
            const float v1 = acc[i * 4 + n][1] + bb.y;
            const float v2 = acc[i * 4 + n][2] + bb.x;
            const float v3 = acc[i * 4 + n][3] + bb.y;
            if (HALF_OUT) {
                __half2 h0 = __floats2half2_rn(v0, v1);
                __half2 h1 = __floats2half2_rn(v2, v3);
                *(__half2*)((__half*)Cv + r0 * N + col)       = h0;
                *(__half2*)((__half*)Cv + (r0 + 8) * N + col) = h1;
            } else {
                *(float2*)((float*)Cv + r0 * N + col)       = make_float2(v0, v1);
                *(float2*)((float*)Cv + (r0 + 8) * N + col) = make_float2(v2, v3);
            }
        }
    }
}

// ---------------------------------------------------------------------------
// WMMA sliding-window attention, 256 threads (8 warps) per 64-query block.
// (unchanged from round 11)
// ---------------------------------------------------------------------------
#define AQ_OFF 0
#define AK_OFF 9216
#define AV_OFF 23040
#define AS_OFF 36864
#define ATT_SMEM 62464

__global__ __launch_bounds__(256)
void attn_wmma()
{
    extern __shared__ __align__(16) char sm[];
    __half* Qh = (__half*)(sm + AQ_OFF);
    __half* Kh = (__half*)(sm + AK_OFF);
    __half* Vh = (__half*)(sm + AV_OFF);
    float*  Sf = (float*)(sm + AS_OFF);
    __half* Ph = (__half*)(sm + AK_OFF);   // overlays K (dead after QK)

    const int b  = blockIdx.z;
    const int h  = blockIdx.y;
    const int s0 = blockIdx.x * 64;
    const int tid  = threadIdx.x;
    const int w    = tid >> 5;

    const __half* qbase = g_qkvh + (size_t)(b * KS) * 3072 + h * 192;
#pragma unroll
    for (int u = 0; u < 2; u++) {
        int i = tid + u * 256;
        int r = i >> 3, c = (i & 7) * 8;
        *(uint4*)(Qh + r * 72 + c) = *(const uint4*)(qbase + (size_t)(s0 + r) * 3072 + c);
    }
#pragma unroll
    for (int u = 0; u < 3; u++) {
        int i = tid + u * 256;
        int r = i >> 3, c = (i & 7) * 8;
        int key = s0 - KW + r;
        key = key < 0 ? 0 : (key >= KS ? KS - 1 : key);
        *(uint4*)(Kh + r * 72 + c) = *(const uint4*)(qbase + (size_t)key * 3072 + 64 + c);
    }
#pragma unroll
    for (int u = 0; u < 3; u++) {
        int i = tid + u * 256;
        int r = i >> 3, c = (i & 7) * 8;
        int key = s0 - KW + r;
        key = key < 0 ? 0 : (key >= KS ? KS - 1 : key);
        *(uint4*)(Vh + r * 72 + c) = *(const uint4*)(qbase + (size_t)key * 3072 + 128 + c);
    }
    __syncthreads();

    // S = Q @ K^T : warp w -> rows 16*(w&3), n-tiles (w>>2)*3 .. +2
    {
        const int wr = (w & 3) * 16;
        const int nb = (w >> 2) * 3;
        wmma::fragment<wmma::matrix_a, 16, 16, 16, __half, wmma::row_major> af[4];
#pragma unroll
        for (int k = 0; k < 4; k++)
            wmma::load_matrix_sync(af[k], &Qh[wr * 72 + k * 16], 72);
#pragma unroll
        for (int nn = 0; nn < 3; nn++) {
            const int n = nb + nn;
            wmma::fragment<wmma::accumulator, 16, 16, 16, float> sc;
            wmma::fill_fragment(sc, 0.0f);
#pragma unroll
            for (int k = 0; k < 4; k++) {
                wmma::fragment<wmma::matrix_b, 16, 16, 16, __half, wmma::col_major> bf;
                wmma::load_matrix_sync(bf, &Kh[(n * 16) * 72 + k * 16], 72);
                wmma::mma_sync(sc, af[k], bf, sc);
            }
            wmma::store_matrix_sync(&Sf[wr * 100 + n * 16], sc, 100, wmma::mem_row_major);
        }
    }
    __syncthreads();

    // masked softmax: 4 threads per row
    {
        const int row = tid >> 2;
        const int sub = tid & 3;
        int jlo = row;
        if (s0 - KW + jlo < 0) jlo = KW - s0;
        int jhi = row + 32;
        const int jmax = KS - 1 - s0 + KW;
        if (jhi > jmax) jhi = jmax;
        const int ja = sub * 24;
        const int lo = jlo > ja ? jlo : ja;
        const int hi = jhi < ja + 23 ? jhi : ja + 23;

        float* Srow = Sf + row * 100;
        float m = -1e30f;
        for (int j = lo; j <= hi; j++) m = fmaxf(m, Srow[j]);
        m = fmaxf(m, __shfl_xor_sync(0xffffffffu, m, 1));
        m = fmaxf(m, __shfl_xor_sync(0xffffffffu, m, 2));
        float s = 0.f;
        for (int j = lo; j <= hi; j++) {
            float e = __expf(0.125f * (Srow[j] - m));
            Srow[j] = e;
            s += e;
        }
        s += __shfl_xor_sync(0xffffffffu, s, 1);
        s += __shfl_xor_sync(0xffffffffu, s, 2);
        const float inv = 1.0f / s;
        __half* Prow = Ph + row * 104;
        for (int j = ja; j < ja + 24; j++) {
            float p = (j >= lo && j <= hi) ? Srow[j] * inv : 0.f;
            Prow[j] = __float2half(p);
        }
    }
    __syncthreads();

    // O = P @ V : warp w -> rows 16*(w&3), cols 32*(w>>2)
    {
        const int wr = (w & 3) * 16;
        const int ch = (w >> 2);
        wmma::fragment<wmma::accumulator, 16, 16, 16, float> of[2];
#pragma unroll
        for (int n = 0; n < 2; n++) wmma::fill_fragment(of[n], 0.0f);
#pragma unroll
        for (int k = 0; k < 6; k++) {
            wmma::fragment<wmma::matrix_a, 16, 16, 16, __half, wmma::row_major> af;
            wmma::load_matrix_sync(af, &Ph[wr * 104 + k * 16], 104);
#pragma unroll
            for (int n = 0; n < 2; n++) {
                wmma::fragment<wmma::matrix_b, 16, 16, 16, __half, wmma::row_major> bf;
                wmma::load_matrix_sync(bf, &Vh[(k * 16) * 72 + (ch * 2 + n) * 16], 72);
                wmma::mma_sync(of[n], af, bf, of[n]);
            }
        }
        float* stg = (float*)(sm + AS_OFF) + w * 320;
        const int lane = tid & 31;
        const int r  = lane >> 1;
        const int c8 = (lane & 1) * 8;
#pragma unroll
        for (int n = 0; n < 2; n++) {
            wmma::store_matrix_sync(stg, of[n], 20, wmma::mem_row_major);
            __syncwarp();
            const float* sp = stg + r * 20 + c8;
            __half2 h0 = __floats2half2_rn(sp[0], sp[1]);
            __half2 h1 = __floats2half2_rn(sp[2], sp[3]);
            __half2 h2 = __floats2half2_rn(sp[4], sp[5]);
            __half2 h3 = __floats2half2_rn(sp[6], sp[7]);
            uint4 u;
            u.x = *reinterpret_cast<uint32_t*>(&h0);
            u.y = *reinterpret_cast<uint32_t*>(&h1);
            u.z = *reinterpret_cast<uint32_t*>(&h2);
            u.w = *reinterpret_cast<uint32_t*>(&h3);
            *(uint4*)(g_attnh + (size_t)(b * KS + s0 + wr + r) * KD
                               + h * 64 + (ch * 2 + n) * 16 + c8) = u;
            __syncwarp();
        }
    }
}

// ---------------------------------------------------------------------------
extern "C" void kernel_launch(void* const* d_in, const int* in_sizes, int n_in,
                              void* d_out, int out_size)
{
    const float* x    = (const float*)d_in[0];
    const float* Wqkv = (const float*)d_in[1];
    const float* bqkv = (const float*)d_in[2];
    const float* Wo   = (const float*)d_in[3];
    const float* bo   = (const float*)d_in[4];
    float* out = (float*)d_out;

    void *p_qkvh, *p_xh, *p_attnh, *p_wqkvh, *p_woh;
    cudaGetSymbolAddress(&p_qkvh,  g_qkvh);
    cudaGetSymbolAddress(&p_xh,    g_xh);
    cudaGetSymbolAddress(&p_attnh, g_attnh);
    cudaGetSymbolAddress(&p_wqkvh, g_wqkvh);
    cudaGetSymbolAddress(&p_woh,   g_woh);

    cudaFuncSetAttribute(gemm_mma<true>,  cudaFuncAttributeMaxDynamicSharedMemorySize, G_SMEM);
    cudaFuncSetAttribute(gemm_mma<false>, cudaFuncAttributeMaxDynamicSharedMemorySize, G_SMEM);
    cudaFuncSetAttribute(attn_wmma, cudaFuncAttributeMaxDynamicSharedMemorySize, ATT_SMEM);

    // 0) fp32 -> fp16 converts
    f2h<<<4096, 256>>>(x,    (__half*)p_xh,    KM * KD);
    f2h<<<1024, 256>>>(Wqkv, (__half*)p_wqkvh, 1024 * 3072);
    f2h<<<512,  256>>>(Wo,   (__half*)p_woh,   1024 * 1024);

    // 1) QKV projection (fp16 out): g_qkvh = x @ Wqkv + bqkv
    gemm_mma<true><<<dim3(3072 / 128, KM / 128), 256, G_SMEM>>>(
        (const __half*)p_xh, (const __half*)p_wqkvh, bqkv, p_qkvh, 3072, 1024);

    // 2) WMMA sliding-window attention -> g_attnh
    attn_wmma<<<dim3(KS / 64, KH, KB), 256, ATT_SMEM>>>();

    // 3) Output projection (fp32 out): out = g_attnh @ Wo + bo
    gemm_mma<false><<<dim3(1024 / 128, KM / 128), 256, G_SMEM>>>(
        (const __half*)p_attnh, (const __half*)p_woh, bo, out, 1024, 1024);
}

// round 13
// speedup vs baseline: 1.0899x; 1.0899x over previous
#include <cuda_runtime.h>
#include <cuda_fp16.h>
#include <mma.h>
#include <math_constants.h>
#include <cstdint>
#include <cstddef>

using namespace nvcuda;

// Problem constants
#define KB 8
#define KS 4096
#define KH 16
#define KD 1024
#define KM 32768      // B*S
#define KW 16

// Device scratch (allocation-free rules)
__device__ __align__(256) __half g_qkvh [(size_t)KM * 3072];  // fp16 QKV (+bias)
__device__ __align__(256) __half g_xh   [(size_t)KM * KD];    // x in fp16
__device__ __align__(256) __half g_attnh[(size_t)KM * KD];    // attention out fp16
__device__ __align__(256) __half g_wqkvh[1024 * 3072];        // Wqkv fp16 [K][N]
__device__ __align__(256) __half g_woh  [1024 * 1024];        // Wo   fp16 [K][N]

// ---------------------------------------------------------------------------
// cp.async helpers
// ---------------------------------------------------------------------------
__device__ __forceinline__ uint32_t smem_u32(const void* p) {
    return (uint32_t)__cvta_generic_to_shared((void*)p);
}
__device__ __forceinline__ void cp_async16(uint32_t dst, const void* src) {
    asm volatile("cp.async.cg.shared.global [%0], [%1], 16;\n" :: "r"(dst), "l"(src) : "memory");
}
__device__ __forceinline__ void cp_commit() { asm volatile("cp.async.commit_group;\n" ::: "memory"); }
__device__ __forceinline__ void cp_wait0()  { asm volatile("cp.async.wait_group 0;\n" ::: "memory"); }
__device__ __forceinline__ void cp_wait1()  { asm volatile("cp.async.wait_group 1;\n" ::: "memory"); }

// ---------------------------------------------------------------------------
// fp32 -> fp16 convert
// ---------------------------------------------------------------------------
__global__ void f2h(const float* __restrict__ in, __half* __restrict__ out, int n)
{
    int i = (blockIdx.x * blockDim.x + threadIdx.x) * 4;
    const int stride = gridDim.x * blockDim.x * 4;
    for (; i < n; i += stride) {
        float4 v = *(const float4*)(in + i);
        __half2 h0 = __floats2half2_rn(v.x, v.y);
        __half2 h1 = __floats2half2_rn(v.z, v.w);
        uint2 u;
        u.x = *reinterpret_cast<uint32_t*>(&h0);
        u.y = *reinterpret_cast<uint32_t*>(&h1);
        *(uint2*)(out + i) = u;
    }
}

// ---------------------------------------------------------------------------
// Common stage geometry (BK=64)
// ---------------------------------------------------------------------------
#define G_LDA 72                     // A row stride (halves)
#define G_LDB 136                    // B row stride (halves)
#define G_ASZ (128 * G_LDA * 2)      // 18432
#define G_STG (G_ASZ + 64 * G_LDB * 2)   // 35840
#define G_SMEM (3 * G_STG)           // 107520

// ---------------------------------------------------------------------------
// GEMM variant A (proven, round 11): 256 thr, 8 warps 2x4, warp tile 64x32.
// Used for the output projection.
// ---------------------------------------------------------------------------
template<bool HALF_OUT>
__global__ __launch_bounds__(256, 2)
void gemm_k64(const __half* __restrict__ A, const __half* __restrict__ Bw,
              const float* __restrict__ bias, void* __restrict__ Cv,
              int N, int K)
{
    extern __shared__ __align__(16) char sm[];
    const uint32_t sbase = smem_u32(sm);
    const int tid    = threadIdx.x;
    const int warpId = tid >> 5;
    const int lane   = tid & 31;
    const int warpM  = warpId & 1;
    const int warpN  = warpId >> 1;
    const int m0 = blockIdx.y * 128;
    const int n0 = blockIdx.x * 128;
    const int nT = K >> 6;

    auto fill = [&](int t, int slot) {
        const int k0 = t << 6;
        const uint32_t sb = sbase + (uint32_t)slot * G_STG;
#pragma unroll
        for (int u = 0; u < 4; u++) {
            int i = tid + u * 256;
            int r = i >> 3, c = (i & 7) * 8;
            cp_async16(sb + r * (G_LDA * 2) + c * 2, A + (size_t)(m0 + r) * K + k0 + c);
        }
#pragma unroll
        for (int u = 0; u < 4; u++) {
            int i = tid + u * 256;
            int r = i >> 4, c = (i & 15) * 8;
            cp_async16(sb + G_ASZ + r * (G_LDB * 2) + c * 2,
                       Bw + (size_t)(k0 + r) * N + n0 + c);
        }
    };

    fill(0, 0); cp_commit();
    fill(1, 1); cp_commit();

    wmma::fragment<wmma::accumulator, 16, 16, 16, float> cf[4][2];
#pragma unroll
    for (int i = 0; i < 4; i++)
#pragma unroll
        for (int j = 0; j < 2; j++)
            wmma::fill_fragment(cf[i][j], 0.0f);

    for (int t = 0; t < nT; t++) {
        const int slot = t % 3;
        if (t + 1 < nT) cp_wait1(); else cp_wait0();
        __syncthreads();
        if (t + 2 < nT) { fill(t + 2, (t + 2) % 3); cp_commit(); }

        const __half* As_ = (const __half*)(sm + (size_t)slot * G_STG);
        const __half* Bs_ = (const __half*)(sm + (size_t)slot * G_STG + G_ASZ);
#pragma unroll
        for (int kk = 0; kk < 4; kk++) {
            wmma::fragment<wmma::matrix_b, 16, 16, 16, __half, wmma::row_major> bf[2];
#pragma unroll
            for (int j = 0; j < 2; j++)
                wmma::load_matrix_sync(bf[j], &Bs_[(kk * 16) * G_LDB + warpN * 32 + j * 16], G_LDB);
#pragma unroll
            for (int i = 0; i < 4; i++) {
                wmma::fragment<wmma::matrix_a, 16, 16, 16, __half, wmma::row_major> af;
                wmma::load_matrix_sync(af, &As_[(warpM * 64 + i * 16) * G_LDA + kk * 16], G_LDA);
#pragma unroll
                for (int j = 0; j < 2; j++)
                    wmma::mma_sync(cf[i][j], af, bf[j], cf[i][j]);
            }
        }
    }

    __syncthreads();

    float* stg = (float*)sm + warpId * 320;
    const int r  = lane >> 1;
    const int c8 = (lane & 1) * 8;
#pragma unroll
    for (int j = 0; j < 2; j++) {
        const float* bp = bias + n0 + warpN * 32 + j * 16 + c8;
        const float4 b0 = *(const float4*)bp;
        const float4 b1 = *(const float4*)(bp + 4);
#pragma unroll
        for (int i = 0; i < 4; i++) {
            wmma::store_matrix_sync(stg, cf[i][j], 20, wmma::mem_row_major);
            __syncwarp();
            const float* s = stg + r * 20 + c8;
            float v0 = s[0] + b0.x, v1 = s[1] + b0.y, v2 = s[2] + b0.z, v3 = s[3] + b0.w;
            float v4 = s[4] + b1.x, v5 = s[5] + b1.y, v6 = s[6] + b1.z, v7 = s[7] + b1.w;
            const size_t row = (size_t)(m0 + warpM * 64 + i * 16 + r);
            const int    col = n0 + warpN * 32 + j * 16 + c8;
            if (HALF_OUT) {
                __half2 h0 = __floats2half2_rn(v0, v1);
                __half2 h1 = __floats2half2_rn(v2, v3);
                __half2 h2 = __floats2half2_rn(v4, v5);
                __half2 h3 = __floats2half2_rn(v6, v7);
                uint4 u;
                u.x = *reinterpret_cast<uint32_t*>(&h0);
                u.y = *reinterpret_cast<uint32_t*>(&h1);
                u.z = *reinterpret_cast<uint32_t*>(&h2);
                u.w = *reinterpret_cast<uint32_t*>(&h3);
                *(uint4*)((__half*)Cv + row * N + col) = u;
            } else {
                *(float4*)((float*)Cv + row * N + col)     = make_float4(v0, v1, v2, v3);
                *(float4*)((float*)Cv + row * N + col + 4) = make_float4(v4, v5, v6, v7);
            }
            __syncwarp();
        }
    }
}

// ---------------------------------------------------------------------------
// GEMM variant B (NEW): 128 thr, 4 warps 2x2, warp tile 64x64.
// Halves smem fragment traffic per MAC (0.094 -> 0.0625 B/MAC).
// 2 CTAs/SM (8 warps), 32 back-to-back HMMAs per k-step per warp for ILP.
// Used for the QKV projection (fp16 out).
// ---------------------------------------------------------------------------
template<bool HALF_OUT>
__global__ __launch_bounds__(128, 2)
void gemm_w64(const __half* __restrict__ A, const __half* __restrict__ Bw,
              const float* __restrict__ bias, void* __restrict__ Cv,
              int N, int K)
{
    extern __shared__ __align__(16) char sm[];
    const uint32_t sbase = smem_u32(sm);
    const int tid    = threadIdx.x;
    const int warpId = tid >> 5;      // 0..3
    const int lane   = tid & 31;
    const int wm = warpId & 1;        // 64-row half
    const int wn = warpId >> 1;       // 64-col half
    const int m0 = blockIdx.y * 128;
    const int n0 = blockIdx.x * 128;
    const int nT = K >> 6;

    auto fill = [&](int t, int slot) {
        const int k0 = t << 6;
        const uint32_t sb = sbase + (uint32_t)slot * G_STG;
        // A: 1024 chunks, 8 per thread
#pragma unroll
        for (int u = 0; u < 8; u++) {
            int i = tid + u * 128;
            int r = i >> 3, c = (i & 7) * 8;
            cp_async16(sb + r * (G_LDA * 2) + c * 2, A + (size_t)(m0 + r) * K + k0 + c);
        }
        // B: 1024 chunks, 8 per thread
#pragma unroll
        for (int u = 0; u < 8; u++) {
            int i = tid + u * 128;
            int r = i >> 4, c = (i & 15) * 8;
            cp_async16(sb + G_ASZ + r * (G_LDB * 2) + c * 2,
                       Bw + (size_t)(k0 + r) * N + n0 + c);
        }
    };

    fill(0, 0); cp_commit();
    fill(1, 1); cp_commit();

    wmma::fragment<wmma::accumulator, 16, 16, 16, float> cf[4][4];
#pragma unroll
    for (int i = 0; i < 4; i++)
#pragma unroll
        for (int j = 0; j < 4; j++)
            wmma::fill_fragment(cf[i][j], 0.0f);

    for (int t = 0; t < nT; t++) {
        const int slot = t % 3;
        if (t + 1 < nT) cp_wait1(); else cp_wait0();
        __syncthreads();
        if (t + 2 < nT) { fill(t + 2, (t + 2) % 3); cp_commit(); }

        const __half* As_ = (const __half*)(sm + (size_t)slot * G_STG);
        const __half* Bs_ = (const __half*)(sm + (size_t)slot * G_STG + G_ASZ);
#pragma unroll
        for (int kk = 0; kk < 4; kk++) {
            wmma::fragment<wmma::matrix_b, 16, 16, 16, __half, wmma::row_major> bf[4];
#pragma unroll
            for (int j = 0; j < 4; j++)
                wmma::load_matrix_sync(bf[j], &Bs_[(kk * 16) * G_LDB + wn * 64 + j * 16], G_LDB);
#pragma unroll
            for (int i = 0; i < 4; i++) {
                wmma::fragment<wmma::matrix_a, 16, 16, 16, __half, wmma::row_major> af;
                wmma::load_matrix_sync(af, &As_[(wm * 64 + i * 16) * G_LDA + kk * 16], G_LDA);
#pragma unroll
                for (int j = 0; j < 4; j++)
                    wmma::mma_sync(cf[i][j], af, bf[j], cf[i][j]);
            }
        }
    }

    __syncthreads();   // stage smem dead -> epilogue staging

    float* stg = (float*)sm + warpId * 320;   // 16x20 per warp
    const int r  = lane >> 1;
    const int c8 = (lane & 1) * 8;
#pragma unroll
    for (int j = 0; j < 4; j++) {
        const float* bp = bias + n0 + wn * 64 + j * 16 + c8;
        const float4 b0 = *(const float4*)bp;
        const float4 b1 = *(const float4*)(bp + 4);
#pragma unroll
        for (int i = 0; i < 4; i++) {
            wmma::store_matrix_sync(stg, cf[i][j], 20, wmma::mem_row_major);
            __syncwarp();
            const float* s = stg + r * 20 + c8;
            float v0 = s[0] + b0.x, v1 = s[1] + b0.y, v2 = s[2] + b0.z, v3 = s[3] + b0.w;
            float v4 = s[4] + b1.x, v5 = s[5] + b1.y, v6 = s[6] + b1.z, v7 = s[7] + b1.w;
            const size_t row = (size_t)(m0 + wm * 64 + i * 16 + r);
            const int    col = n0 + wn * 64 + j * 16 + c8;
            if (HALF_OUT) {
                __half2 h0 = __floats2half2_rn(v0, v1);
                __half2 h1 = __floats2half2_rn(v2, v3);
                __half2 h2 = __floats2half2_rn(v4, v5);
                __half2 h3 = __floats2half2_rn(v6, v7);
                uint4 u;
                u.x = *reinterpret_cast<uint32_t*>(&h0);
                u.y = *reinterpret_cast<uint32_t*>(&h1);
                u.z = *reinterpret_cast<uint32_t*>(&h2);
                u.w = *reinterpret_cast<uint32_t*>(&h3);
                *(uint4*)((__half*)Cv + row * N + col) = u;
            } else {
                *(float4*)((float*)Cv + row * N + col)     = make_float4(v0, v1, v2, v3);
                *(float4*)((float*)Cv + row * N + col + 4) = make_float4(v4, v5, v6, v7);
            }
            __syncwarp();
        }
    }
}

// ---------------------------------------------------------------------------
// WMMA sliding-window attention, 256 threads (8 warps) per 64-query block.
// (unchanged from round 11)
// ---------------------------------------------------------------------------
#define AQ_OFF 0
#define AK_OFF 9216
#define AV_OFF 23040
#define AS_OFF 36864
#define ATT_SMEM 62464

__global__ __launch_bounds__(256)
void attn_wmma()
{
    extern __shared__ __align__(16) char sm[];
    __half* Qh = (__half*)(sm + AQ_OFF);
    __half* Kh = (__half*)(sm + AK_OFF);
    __half* Vh = (__half*)(sm + AV_OFF);
    float*  Sf = (float*)(sm + AS_OFF);
    __half* Ph = (__half*)(sm + AK_OFF);   // overlays K (dead after QK)

    const int b  = blockIdx.z;
    const int h  = blockIdx.y;
    const int s0 = blockIdx.x * 64;
    const int tid  = threadIdx.x;
    const int w    = tid >> 5;

    const __half* qbase = g_qkvh + (size_t)(b * KS) * 3072 + h * 192;
#pragma unroll
    for (int u = 0; u < 2; u++) {
        int i = tid + u * 256;
        int r = i >> 3, c = (i & 7) * 8;
        *(uint4*)(Qh + r * 72 + c) = *(const uint4*)(qbase + (size_t)(s0 + r) * 3072 + c);
    }
#pragma unroll
    for (int u = 0; u < 3; u++) {
        int i = tid + u * 256;
        int r = i >> 3, c = (i & 7) * 8;
        int key = s0 - KW + r;
        key = key < 0 ? 0 : (key >= KS ? KS - 1 : key);
        *(uint4*)(Kh + r * 72 + c) = *(const uint4*)(qbase + (size_t)key * 3072 + 64 + c);
    }
#pragma unroll
    for (int u = 0; u < 3; u++) {
        int i = tid + u * 256;
        int r = i >> 3, c = (i & 7) * 8;
        int key = s0 - KW + r;
        key = key < 0 ? 0 : (key >= KS ? KS - 1 : key);
        *(uint4*)(Vh + r * 72 + c) = *(const uint4*)(qbase + (size_t)key * 3072 + 128 + c);
    }
    __syncthreads();

    // S = Q @ K^T
    {
        const int wr = (w & 3) * 16;
        const int nb = (w >> 2) * 3;
        wmma::fragment<wmma::matrix_a, 16, 16, 16, __half, wmma::row_major> af[4];
#pragma unroll
        for (int k = 0; k < 4; k++)
            wmma::load_matrix_sync(af[k], &Qh[wr * 72 + k * 16], 72);
#pragma unroll
        for (int nn = 0; nn < 3; nn++) {
            const int n = nb + nn;
            wmma::fragment<wmma::accumulator, 16, 16, 16, float> sc;
            wmma::fill_fragment(sc, 0.0f);
#pragma unroll
            for (int k = 0; k < 4; k++) {
                wmma::fragment<wmma::matrix_b, 16, 16, 16, __half, wmma::col_major> bf;
                wmma::load_matrix_sync(bf, &Kh[(n * 16) * 72 + k * 16], 72);
                wmma::mma_sync(sc, af[k], bf, sc);
            }
            wmma::store_matrix_sync(&Sf[wr * 100 + n * 16], sc, 100, wmma::mem_row_major);
        }
    }
    __syncthreads();

    // masked softmax
    {
        const int row = tid >> 2;
        const int sub = tid & 3;
        int jlo = row;
        if (s0 - KW + jlo < 0) jlo = KW - s0;
        int jhi = row + 32;
        const int jmax = KS - 1 - s0 + KW;
        if (jhi > jmax) jhi = jmax;
        const int ja = sub * 24;
        const int lo = jlo > ja ? jlo : ja;
        const int hi = jhi < ja + 23 ? jhi : ja + 23;

        float* Srow = Sf + row * 100;
        float m = -1e30f;
        for (int j = lo; j <= hi; j++) m = fmaxf(m, Srow[j]);
        m = fmaxf(m, __shfl_xor_sync(0xffffffffu, m, 1));
        m = fmaxf(m, __shfl_xor_sync(0xffffffffu, m, 2));
        float s = 0.f;
        for (int j = lo; j <= hi; j++) {
            float e = __expf(0.125f * (Srow[j] - m));
            Srow[j] = e;
            s += e;
        }
        s += __shfl_xor_sync(0xffffffffu, s, 1);
        s += __shfl_xor_sync(0xffffffffu, s, 2);
        const float inv = 1.0f / s;
        __half* Prow = Ph + row * 104;
        for (int j = ja; j < ja + 24; j++) {
            float p = (j >= lo && j <= hi) ? Srow[j] * inv : 0.f;
            Prow[j] = __float2half(p);
        }
    }
    __syncthreads();

    // O = P @ V
    {
        const int wr = (w & 3) * 16;
        const int ch = (w >> 2);
        wmma::fragment<wmma::accumulator, 16, 16, 16, float> of[2];
#pragma unroll
        for (int n = 0; n < 2; n++) wmma::fill_fragment(of[n], 0.0f);
#pragma unroll
        for (int k = 0; k < 6; k++) {
            wmma::fragment<wmma::matrix_a, 16, 16, 16, __half, wmma::row_major> af;
            wmma::load_matrix_sync(af, &Ph[wr * 104 + k * 16], 104);
#pragma unroll
            for (int n = 0; n < 2; n++) {
                wmma::fragment<wmma::matrix_b, 16, 16, 16, __half, wmma::row_major> bf;
                wmma::load_matrix_sync(bf, &Vh[(k * 16) * 72 + (ch * 2 + n) * 16], 72);
                wmma::mma_sync(of[n], af, bf, of[n]);
            }
        }
        float* stg = (float*)(sm + AS_OFF) + w * 320;
        const int lane = tid & 31;
        const int r  = lane >> 1;
        const int c8 = (lane & 1) * 8;
#pragma unroll
        for (int n = 0; n < 2; n++) {
            wmma::store_matrix_sync(stg, of[n], 20, wmma::mem_row_major);
            __syncwarp();
            const float* sp = stg + r * 20 + c8;
            __half2 h0 = __floats2half2_rn(sp[0], sp[1]);
            __half2 h1 = __floats2half2_rn(sp[2], sp[3]);
            __half2 h2 = __floats2half2_rn(sp[4], sp[5]);
            __half2 h3 = __floats2half2_rn(sp[6], sp[7]);
            uint4 u;
            u.x = *reinterpret_cast<uint32_t*>(&h0);
            u.y = *reinterpret_cast<uint32_t*>(&h1);
            u.z = *reinterpret_cast<uint32_t*>(&h2);
            u.w = *reinterpret_cast<uint32_t*>(&h3);
            *(uint4*)(g_attnh + (size_t)(b * KS + s0 + wr + r) * KD
                               + h * 64 + (ch * 2 + n) * 16 + c8) = u;
            __syncwarp();
        }
    }
}

// ---------------------------------------------------------------------------
extern "C" void kernel_launch(void* const* d_in, const int* in_sizes, int n_in,
                              void* d_out, int out_size)
{
    const float* x    = (const float*)d_in[0];
    const float* Wqkv = (const float*)d_in[1];
    const float* bqkv = (const float*)d_in[2];
    const float* Wo   = (const float*)d_in[3];
    const float* bo   = (const float*)d_in[4];
    float* out = (float*)d_out;

    void *p_qkvh, *p_xh, *p_attnh, *p_wqkvh, *p_woh;
    cudaGetSymbolAddress(&p_qkvh,  g_qkvh);
    cudaGetSymbolAddress(&p_xh,    g_xh);
    cudaGetSymbolAddress(&p_attnh, g_attnh);
    cudaGetSymbolAddress(&p_wqkvh, g_wqkvh);
    cudaGetSymbolAddress(&p_woh,   g_woh);

    cudaFuncSetAttribute(gemm_w64<true>,  cudaFuncAttributeMaxDynamicSharedMemorySize, G_SMEM);
    cudaFuncSetAttribute(gemm_k64<false>, cudaFuncAttributeMaxDynamicSharedMemorySize, G_SMEM);
    cudaFuncSetAttribute(attn_wmma, cudaFuncAttributeMaxDynamicSharedMemorySize, ATT_SMEM);

    // 0) fp32 -> fp16 converts
    f2h<<<4096, 256>>>(x,    (__half*)p_xh,    KM * KD);
    f2h<<<1024, 256>>>(Wqkv, (__half*)p_wqkvh, 1024 * 3072);
    f2h<<<512,  256>>>(Wo,   (__half*)p_woh,   1024 * 1024);

    // 1) QKV projection (fp16 out): 64x64-warp-tile variant
    gemm_w64<true><<<dim3(3072 / 128, KM / 128), 128, G_SMEM>>>(
        (const __half*)p_xh, (const __half*)p_wqkvh, bqkv, p_qkvh, 3072, 1024);

    // 2) WMMA sliding-window attention -> g_attnh
    attn_wmma<<<dim3(KS / 64, KH, KB), 256, ATT_SMEM>>>();

    // 3) Output projection (fp32 out): proven 64x32-warp-tile variant
    gemm_k64<false><<<dim3(1024 / 128, KM / 128), 256, G_SMEM>>>(
        (const __half*)p_attnh, (const __half*)p_woh, bo, out, 1024, 1024);
}